// round 2
// baseline (speedup 1.0000x reference)
#include <cuda_runtime.h>
#include <cstdint>

#define NODES 50000
#define D 128
#define C 40

// Scratch (no cudaMalloc allowed)
__device__ float g_S1[NODES * D];   // x @ W1
__device__ float g_H [NODES * D];   // aggregated + relu
__device__ float g_S2[NODES * C];   // h @ W2

// ---------------- zero ----------------
__global__ void zero_H_kernel(int n) {
    int i = blockIdx.x * blockDim.x + threadIdx.x;
    if (i < n) g_H[i] = 0.0f;
}
__global__ void zero_out_kernel(float* p, int n) {
    int i = blockIdx.x * blockDim.x + threadIdx.x;
    if (i < n) p[i] = 0.0f;
}

// ---------------- GEMM1: S1 = x @ W1  (block per row, 128 threads) ----------------
__global__ void gemm1_kernel(const float* __restrict__ x,
                             const float* __restrict__ W1) {
    __shared__ float xs[D];
    int r = blockIdx.x;
    int j = threadIdx.x;
    xs[j] = x[r * D + j];
    __syncthreads();
    float sum = 0.0f;
#pragma unroll 16
    for (int k = 0; k < D; k++)
        sum = fmaf(xs[k], W1[k * D + j], sum);
    g_S1[r * D + j] = sum;
}

// ---------------- SpMM layer1: warp per edge, red.v4 atomics ----------------
__global__ void spmm1_kernel(const int* __restrict__ ei,
                             const float* __restrict__ ew,
                             int E) {
    int gtid = blockIdx.x * blockDim.x + threadIdx.x;
    int e    = gtid >> 5;        // warp per edge
    int lane = gtid & 31;        // one float4 per lane (32*4 = 128 cols)
    if (e >= E) return;
    int row = ei[e];
    int col = ei[E + e];
    float w = ew[e];
    const float4* src = reinterpret_cast<const float4*>(g_S1 + (long long)col * D);
    float4 v = src[lane];
    float* dst = g_H + (long long)row * D + lane * 4;
    asm volatile("red.global.add.v4.f32 [%0], {%1,%2,%3,%4};"
                 :: "l"(dst), "f"(v.x * w), "f"(v.y * w), "f"(v.z * w), "f"(v.w * w)
                 : "memory");
}

// ---------------- bias + relu ----------------
__global__ void bias_relu_kernel(const float* __restrict__ b1, int n) {
    int i = blockIdx.x * blockDim.x + threadIdx.x;
    if (i < n) {
        float v = g_H[i] + b1[i & (D - 1)];
        g_H[i] = v > 0.0f ? v : 0.0f;
    }
}

// ---------------- GEMM2: S2 = H @ W2  (block per row, 64 threads) ----------------
__global__ void gemm2_kernel(const float* __restrict__ W2) {
    __shared__ float hs[D];
    int r = blockIdx.x;
    int t = threadIdx.x;
    hs[t]      = g_H[r * D + t];
    hs[t + 64] = g_H[r * D + t + 64];
    __syncthreads();
    if (t < C) {
        float sum = 0.0f;
#pragma unroll 16
        for (int k = 0; k < D; k++)
            sum = fmaf(hs[k], W2[k * C + t], sum);
        g_S2[r * C + t] = sum;
    }
}

// ---------------- SpMM layer2: 16 threads/edge, 10 active float4 chunks ----------------
__global__ void spmm2_kernel(const int* __restrict__ ei,
                             const float* __restrict__ ew,
                             float* __restrict__ out,
                             int E) {
    int gtid = blockIdx.x * blockDim.x + threadIdx.x;
    int e = gtid >> 4;
    int c = gtid & 15;           // chunk id; 10 active (40 floats)
    if (e >= E || c >= 10) return;
    int row = ei[e];
    int col = ei[E + e];
    float w = ew[e];
    const float4* src = reinterpret_cast<const float4*>(g_S2 + (long long)col * C);
    float4 v = src[c];
    float* dst = out + (long long)row * C + c * 4;
    asm volatile("red.global.add.v4.f32 [%0], {%1,%2,%3,%4};"
                 :: "l"(dst), "f"(v.x * w), "f"(v.y * w), "f"(v.z * w), "f"(v.w * w)
                 : "memory");
}

// ---------------- final: + b2, log_softmax (warp per row) ----------------
__global__ void logsoftmax_kernel(float* __restrict__ out,
                                  const float* __restrict__ b2, int n) {
    int gtid = blockIdx.x * blockDim.x + threadIdx.x;
    int r    = gtid >> 5;
    int lane = gtid & 31;
    if (r >= n) return;
    float* rowp = out + (long long)r * C;
    float v0 = (lane < C) ? rowp[lane] + b2[lane] : -INFINITY;
    float v1 = (lane + 32 < C) ? rowp[lane + 32] + b2[lane + 32] : -INFINITY;
    float m = fmaxf(v0, v1);
#pragma unroll
    for (int off = 16; off > 0; off >>= 1)
        m = fmaxf(m, __shfl_xor_sync(0xffffffff, m, off));
    float s = 0.0f;
    if (lane < C) s += __expf(v0 - m);
    if (lane + 32 < C) s += __expf(v1 - m);
#pragma unroll
    for (int off = 16; off > 0; off >>= 1)
        s += __shfl_xor_sync(0xffffffff, s, off);
    float lse = m + __logf(s);
    if (lane < C) rowp[lane] = v0 - lse;
    if (lane + 32 < C) rowp[lane + 32] = v1 - lse;
}

extern "C" void kernel_launch(void* const* d_in, const int* in_sizes, int n_in,
                              void* d_out, int out_size) {
    const float* x  = (const float*)d_in[0];
    const int*   ei = (const int*)d_in[1];     // int64 in reference -> delivered as int32
    const float* ew = (const float*)d_in[2];
    const float* W1 = (const float*)d_in[3];
    const float* b1 = (const float*)d_in[4];
    const float* W2 = (const float*)d_in[5];
    const float* b2 = (const float*)d_in[6];
    float* out = (float*)d_out;

    int n = in_sizes[0] / D;          // 50000
    int E = in_sizes[1] / 2;          // 1.6M

    // 1. S1 = x @ W1
    gemm1_kernel<<<n, D>>>(x, W1);

    // 2. H = 0; scatter-aggregate layer 1
    {
        int tot = n * D;
        zero_H_kernel<<<(tot + 255) / 256, 256>>>(tot);
        long long threads = (long long)E * 32;
        int blocks = (int)((threads + 255) / 256);
        spmm1_kernel<<<blocks, 256>>>(ei, ew, E);
    }

    // 3. H = relu(H + b1)
    {
        int tot = n * D;
        bias_relu_kernel<<<(tot + 255) / 256, 256>>>(b1, tot);
    }

    // 4. S2 = H @ W2
    gemm2_kernel<<<n, 64>>>(W2);

    // 5. out = 0; scatter-aggregate layer 2
    {
        int tot = n * C;
        zero_out_kernel<<<(tot + 255) / 256, 256>>>(out, tot);
        long long threads = (long long)E * 16;
        int blocks = (int)((threads + 255) / 256);
        spmm2_kernel<<<blocks, 256>>>(ei, ew, out, E);
    }

    // 6. + b2, log_softmax in place
    {
        long long threads = (long long)n * 32;
        int blocks = (int)((threads + 255) / 256);
        logsoftmax_kernel<<<blocks, 256>>>(out, b2, n);
    }
}

// round 3
// speedup vs baseline: 2.0978x; 2.0978x over previous
#include <cuda_runtime.h>
#include <cstdint>
#include <math_constants.h>

#define NODES 50000
#define D 128
#define C 40
#define EDGES_MAX 1600000
#define SCAN_B 49          // 49 * 1024 = 50176 >= NODES
#define SCAN_PAD 50176

// ---------------- scratch (__device__ globals; no allocations allowed) ---------
__device__ float g_S1[NODES * D];       // x @ W1
__device__ float g_H [NODES * D];       // relu(agg + b1)
__device__ float g_S2[NODES * C];       // H @ W2
__device__ int   g_cnt[SCAN_PAD];
__device__ int   g_scanA[SCAN_PAD];
__device__ int   g_bsum[64];
__device__ int   g_bsum_ex[64];
__device__ int   g_rs[NODES + 1];       // CSR row offsets
__device__ int   g_cur[NODES];          // scatter cursors
__device__ int2  g_edge[EDGES_MAX];     // packed {col, weight-bits}, CSR order

// ================= CSR build =================
__global__ void zero_cnt_kernel() {
    int i = blockIdx.x * blockDim.x + threadIdx.x;
    if (i < SCAN_PAD) g_cnt[i] = 0;
}

__global__ void hist_kernel(const int* __restrict__ ei, int E) {
    int e = blockIdx.x * blockDim.x + threadIdx.x;
    if (e < E) atomicAdd(&g_cnt[ei[e]], 1);
}

__global__ void scanA_kernel() {
    __shared__ int sh[1024];
    int t = threadIdx.x;
    int i = blockIdx.x * 1024 + t;
    int v = g_cnt[i];
    sh[t] = v;
    __syncthreads();
#pragma unroll
    for (int off = 1; off < 1024; off <<= 1) {
        int add = (t >= off) ? sh[t - off] : 0;
        __syncthreads();
        sh[t] += add;
        __syncthreads();
    }
    g_scanA[i] = sh[t];
    if (t == 1023) g_bsum[blockIdx.x] = sh[1023];
}

__global__ void scanB_kernel() {
    if (threadIdx.x == 0) {
        int run = 0;
        for (int b = 0; b < SCAN_B; b++) { g_bsum_ex[b] = run; run += g_bsum[b]; }
    }
}

__global__ void scanC_kernel() {
    int t = threadIdx.x;
    int i = blockIdx.x * 1024 + t;
    int incl = g_scanA[i] + g_bsum_ex[blockIdx.x];
    if (i < NODES) {
        int ex = incl - g_cnt[i];
        g_rs[i]  = ex;
        g_cur[i] = ex;
        if (i == NODES - 1) g_rs[NODES] = incl;
    }
}

__global__ void scatter_kernel(const int* __restrict__ ei,
                               const float* __restrict__ ew, int E) {
    int e = blockIdx.x * blockDim.x + threadIdx.x;
    if (e >= E) return;
    int r = ei[e];
    int p = atomicAdd(&g_cur[r], 1);
    g_edge[p] = make_int2(ei[E + e], __float_as_int(ew[e]));
}

// ================= GEMM1: S1 = x @ W1 (64 rows/block, 256 thr, 8r x 4c regs) ===
#define G1_ROWS 64
__global__ void gemm1_kernel(const float* __restrict__ x,
                             const float* __restrict__ W1) {
    __shared__ float xs[G1_ROWS * D];    // 32 KB
    int base = blockIdx.x * G1_ROWS;
    int tid = threadIdx.x;
    const float4* xv = (const float4*)x;
    float4* xsv = (float4*)xs;
    for (int i = tid; i < G1_ROWS * 32; i += 256) {
        int rr = i >> 5, cc = i & 31;
        int r = base + rr;
        xsv[i] = (r < NODES) ? xv[(long long)r * 32 + cc] : make_float4(0, 0, 0, 0);
    }
    __syncthreads();
    int cg = tid & 31;     // float4 column group
    int rg = tid >> 5;     // rows rg*8 .. rg*8+7
    float4 acc[8];
#pragma unroll
    for (int j = 0; j < 8; j++) acc[j] = make_float4(0, 0, 0, 0);
    const float4* Wv = (const float4*)W1;
#pragma unroll 4
    for (int k = 0; k < D; k++) {
        float4 wv = Wv[k * 32 + cg];
#pragma unroll
        for (int j = 0; j < 8; j++) {
            float xr = xs[(rg * 8 + j) * D + k];
            acc[j].x = fmaf(xr, wv.x, acc[j].x);
            acc[j].y = fmaf(xr, wv.y, acc[j].y);
            acc[j].z = fmaf(xr, wv.z, acc[j].z);
            acc[j].w = fmaf(xr, wv.w, acc[j].w);
        }
    }
    float4* S1v = (float4*)g_S1;
#pragma unroll
    for (int j = 0; j < 8; j++) {
        int r = base + rg * 8 + j;
        if (r < NODES) S1v[(long long)r * 32 + cg] = acc[j];
    }
}

// ================= SpMM1 (gather, warp/row) + bias + relu =====================
__global__ void spmm1_kernel(const float* __restrict__ b1) {
    int w = (blockIdx.x * blockDim.x + threadIdx.x) >> 5;
    int lane = threadIdx.x & 31;
    if (w >= NODES) return;
    int i = g_rs[w], end = g_rs[w + 1];
    float4 acc = make_float4(0, 0, 0, 0);
    const float4* S1v = (const float4*)g_S1;
    for (; i + 4 <= end; i += 4) {
        int2 e0 = g_edge[i], e1 = g_edge[i + 1], e2 = g_edge[i + 2], e3 = g_edge[i + 3];
        float4 v0 = S1v[(long long)e0.x * 32 + lane];
        float4 v1 = S1v[(long long)e1.x * 32 + lane];
        float4 v2 = S1v[(long long)e2.x * 32 + lane];
        float4 v3 = S1v[(long long)e3.x * 32 + lane];
        float w0 = __int_as_float(e0.y), w1 = __int_as_float(e1.y);
        float w2 = __int_as_float(e2.y), w3 = __int_as_float(e3.y);
        acc.x = fmaf(w0, v0.x, acc.x); acc.y = fmaf(w0, v0.y, acc.y);
        acc.z = fmaf(w0, v0.z, acc.z); acc.w = fmaf(w0, v0.w, acc.w);
        acc.x = fmaf(w1, v1.x, acc.x); acc.y = fmaf(w1, v1.y, acc.y);
        acc.z = fmaf(w1, v1.z, acc.z); acc.w = fmaf(w1, v1.w, acc.w);
        acc.x = fmaf(w2, v2.x, acc.x); acc.y = fmaf(w2, v2.y, acc.y);
        acc.z = fmaf(w2, v2.z, acc.z); acc.w = fmaf(w2, v2.w, acc.w);
        acc.x = fmaf(w3, v3.x, acc.x); acc.y = fmaf(w3, v3.y, acc.y);
        acc.z = fmaf(w3, v3.z, acc.z); acc.w = fmaf(w3, v3.w, acc.w);
    }
    for (; i < end; i++) {
        int2 e0 = g_edge[i];
        float4 v0 = S1v[(long long)e0.x * 32 + lane];
        float w0 = __int_as_float(e0.y);
        acc.x = fmaf(w0, v0.x, acc.x); acc.y = fmaf(w0, v0.y, acc.y);
        acc.z = fmaf(w0, v0.z, acc.z); acc.w = fmaf(w0, v0.w, acc.w);
    }
    float4 bv = ((const float4*)b1)[lane];
    acc.x = fmaxf(acc.x + bv.x, 0.0f);
    acc.y = fmaxf(acc.y + bv.y, 0.0f);
    acc.z = fmaxf(acc.z + bv.z, 0.0f);
    acc.w = fmaxf(acc.w + bv.w, 0.0f);
    ((float4*)g_H)[(long long)w * 32 + lane] = acc;
}

// ================= GEMM2: S2 = H @ W2 (32 rows/block, 160 thr) ================
#define G2_ROWS 32
__global__ void gemm2_kernel(const float* __restrict__ W2) {
    __shared__ float hs[G2_ROWS * D];    // 16 KB
    int base = blockIdx.x * G2_ROWS;
    int tid = threadIdx.x;                // 160
    float4* hsv = (float4*)hs;
    const float4* Hv = (const float4*)g_H;
    for (int i = tid; i < G2_ROWS * 32; i += 160) {
        int rr = i >> 5, cc = i & 31;
        int r = base + rr;
        hsv[i] = (r < NODES) ? Hv[(long long)r * 32 + cc] : make_float4(0, 0, 0, 0);
    }
    __syncthreads();
    int c = tid % C;
    int rg = tid / C;      // 0..3, rows rg*8..+7
    float acc[8];
#pragma unroll
    for (int j = 0; j < 8; j++) acc[j] = 0.0f;
#pragma unroll 4
    for (int k = 0; k < D; k++) {
        float wv = W2[k * C + c];
#pragma unroll
        for (int j = 0; j < 8; j++)
            acc[j] = fmaf(hs[(rg * 8 + j) * D + k], wv, acc[j]);
    }
#pragma unroll
    for (int j = 0; j < 8; j++) {
        int r = base + rg * 8 + j;
        if (r < NODES) g_S2[(long long)r * C + c] = acc[j];
    }
}

// ============ SpMM2 (gather, half-warp/row) + b2 + log_softmax ================
__global__ void spmm2_kernel(const float* __restrict__ b2,
                             float* __restrict__ out) {
    int gt = blockIdx.x * blockDim.x + threadIdx.x;
    int r = gt >> 4;
    int lane16 = gt & 15;
    if (r >= NODES) return;
    bool act = lane16 < 10;              // 10 float4 chunks cover C=40
    int i = g_rs[r], end = g_rs[r + 1];
    float4 acc = make_float4(0, 0, 0, 0);
    const float4* S2v = (const float4*)g_S2;
    for (; i + 2 <= end; i += 2) {
        int2 e0 = g_edge[i], e1 = g_edge[i + 1];
        if (act) {
            float4 v0 = S2v[(long long)e0.x * 10 + lane16];
            float4 v1 = S2v[(long long)e1.x * 10 + lane16];
            float w0 = __int_as_float(e0.y), w1 = __int_as_float(e1.y);
            acc.x = fmaf(w0, v0.x, acc.x); acc.y = fmaf(w0, v0.y, acc.y);
            acc.z = fmaf(w0, v0.z, acc.z); acc.w = fmaf(w0, v0.w, acc.w);
            acc.x = fmaf(w1, v1.x, acc.x); acc.y = fmaf(w1, v1.y, acc.y);
            acc.z = fmaf(w1, v1.z, acc.z); acc.w = fmaf(w1, v1.w, acc.w);
        }
    }
    for (; i < end; i++) {
        int2 e0 = g_edge[i];
        if (act) {
            float4 v0 = S2v[(long long)e0.x * 10 + lane16];
            float w0 = __int_as_float(e0.y);
            acc.x = fmaf(w0, v0.x, acc.x); acc.y = fmaf(w0, v0.y, acc.y);
            acc.z = fmaf(w0, v0.z, acc.z); acc.w = fmaf(w0, v0.w, acc.w);
        }
    }
    // + bias
    float4 v = make_float4(0, 0, 0, 0);
    if (act) {
        float4 bv = ((const float4*)b2)[lane16];
        v.x = acc.x + bv.x; v.y = acc.y + bv.y;
        v.z = acc.z + bv.z; v.w = acc.w + bv.w;
    }
    // log_softmax over the 40 values held by lanes 0..9 of this 16-lane group
    float m = act ? fmaxf(fmaxf(v.x, v.y), fmaxf(v.z, v.w)) : -CUDART_INF_F;
#pragma unroll
    for (int off = 8; off > 0; off >>= 1)
        m = fmaxf(m, __shfl_xor_sync(0xffffffffu, m, off, 16));
    float s = act ? (__expf(v.x - m) + __expf(v.y - m) +
                     __expf(v.z - m) + __expf(v.w - m)) : 0.0f;
#pragma unroll
    for (int off = 8; off > 0; off >>= 1)
        s += __shfl_xor_sync(0xffffffffu, s, off, 16);
    float lse = m + __logf(s);
    if (act) {
        float4 o;
        o.x = v.x - lse; o.y = v.y - lse; o.z = v.z - lse; o.w = v.w - lse;
        ((float4*)out)[(long long)r * 10 + lane16] = o;
    }
}

// =============================================================================
extern "C" void kernel_launch(void* const* d_in, const int* in_sizes, int n_in,
                              void* d_out, int out_size) {
    const float* x  = (const float*)d_in[0];
    const int*   ei = (const int*)d_in[1];    // delivered as int32
    const float* ew = (const float*)d_in[2];
    const float* W1 = (const float*)d_in[3];
    const float* b1 = (const float*)d_in[4];
    const float* W2 = (const float*)d_in[5];
    const float* b2 = (const float*)d_in[6];
    float* out = (float*)d_out;

    int n = in_sizes[0] / D;      // 50000
    int E = in_sizes[1] / 2;      // 1.6M

    // ---- CSR build ----
    zero_cnt_kernel<<<(SCAN_PAD + 255) / 256, 256>>>();
    hist_kernel<<<(E + 255) / 256, 256>>>(ei, E);
    scanA_kernel<<<SCAN_B, 1024>>>();
    scanB_kernel<<<1, 32>>>();
    scanC_kernel<<<SCAN_B, 1024>>>();
    scatter_kernel<<<(E + 255) / 256, 256>>>(ei, ew, E);

    // ---- layer 1 ----
    gemm1_kernel<<<(n + G1_ROWS - 1) / G1_ROWS, 256>>>(x, W1);
    {
        long long threads = (long long)n * 32;
        spmm1_kernel<<<(int)((threads + 255) / 256), 256>>>(b1);
    }

    // ---- layer 2 ----
    gemm2_kernel<<<(n + G2_ROWS - 1) / G2_ROWS, 160>>>(W2);
    {
        long long threads = (long long)n * 16;
        spmm2_kernel<<<(int)((threads + 255) / 256), 256>>>(b2, out);
    }
}

// round 4
// speedup vs baseline: 2.3571x; 1.1236x over previous
#include <cuda_runtime.h>
#include <cuda_fp16.h>
#include <cstdint>
#include <math_constants.h>

#define NODES 50000
#define D 128
#define C 40
#define EDGES_MAX 1600000
#define SCAN_B 49          // 49 * 1024 = 50176 >= NODES
#define SCAN_PAD 50176

// ---------------- scratch (__device__ globals; no allocations allowed) ---------
__device__ __half g_S1h[NODES * D];     // x @ W1   (fp16 storage)
__device__ float  g_H [NODES * D];      // relu(agg + b1)  (fp32)
__device__ __half g_S2h[NODES * C];     // H @ W2   (fp16 storage)
__device__ int    g_cnt[SCAN_PAD];
__device__ int    g_scanA[SCAN_PAD];
__device__ int    g_bsum[64];
__device__ int    g_rs[NODES + 1];      // CSR row offsets
__device__ int    g_cur[NODES];         // scatter cursors
__device__ int2   g_edge[EDGES_MAX];    // packed {col, weight-bits}, CSR order

// ================= CSR build =================
__global__ void zero_cnt_kernel() {
    int i = blockIdx.x * blockDim.x + threadIdx.x;
    if (i < SCAN_PAD) g_cnt[i] = 0;
}

__global__ void hist_kernel(const int* __restrict__ ei, int E) {
    int e = blockIdx.x * blockDim.x + threadIdx.x;
    if (e < E) atomicAdd(&g_cnt[ei[e]], 1);
}

__global__ void scanA_kernel() {
    __shared__ int sh[1024];
    int t = threadIdx.x;
    int i = blockIdx.x * 1024 + t;
    sh[t] = g_cnt[i];
    __syncthreads();
#pragma unroll
    for (int off = 1; off < 1024; off <<= 1) {
        int add = (t >= off) ? sh[t - off] : 0;
        __syncthreads();
        sh[t] += add;
        __syncthreads();
    }
    g_scanA[i] = sh[t];
    if (t == 1023) g_bsum[blockIdx.x] = sh[1023];
}

// scanC also computes this block's exclusive block-offset (49 independent loads)
__global__ void scanC_kernel() {
    __shared__ int s_off;
    int t = threadIdx.x;
    if (t < 64) {
        int v = (t < (int)blockIdx.x) ? g_bsum[t] : 0;
        // reduce 64 values via shuffles + shared
        __shared__ int warp_s[2];
#pragma unroll
        for (int off = 16; off > 0; off >>= 1)
            v += __shfl_down_sync(0xffffffffu, v, off);
        if ((t & 31) == 0) warp_s[t >> 5] = v;
        __syncthreads();
        if (t == 0) s_off = warp_s[0] + warp_s[1];
    }
    __syncthreads();
    int i = blockIdx.x * 1024 + t;
    int incl = g_scanA[i] + s_off;
    if (i < NODES) {
        int ex = incl - g_cnt[i];
        g_rs[i]  = ex;
        g_cur[i] = ex;
        if (i == NODES - 1) g_rs[NODES] = incl;
    }
}

__global__ void scatter_kernel(const int* __restrict__ ei,
                               const float* __restrict__ ew, int E) {
    int e = blockIdx.x * blockDim.x + threadIdx.x;
    if (e >= E) return;
    int r = ei[e];
    int p = atomicAdd(&g_cur[r], 1);
    g_edge[p] = make_int2(ei[E + e], __float_as_int(ew[e]));
}

// ================= GEMM1: S1 = x @ W1 (64 rows/block, 256 thr, 8r x 4c regs) ===
#define G1_ROWS 64
__global__ void gemm1_kernel(const float* __restrict__ x,
                             const float* __restrict__ W1) {
    __shared__ float xs[G1_ROWS * D];    // 32 KB
    int base = blockIdx.x * G1_ROWS;
    int tid = threadIdx.x;
    const float4* xv = (const float4*)x;
    float4* xsv = (float4*)xs;
    for (int i = tid; i < G1_ROWS * 32; i += 256) {
        int rr = i >> 5, cc = i & 31;
        int r = base + rr;
        xsv[i] = (r < NODES) ? xv[(long long)r * 32 + cc] : make_float4(0, 0, 0, 0);
    }
    __syncthreads();
    int cg = tid & 31;     // float4 column group (cols 4cg..4cg+3)
    int rg = tid >> 5;     // rows rg*8 .. rg*8+7
    float4 acc[8];
#pragma unroll
    for (int j = 0; j < 8; j++) acc[j] = make_float4(0, 0, 0, 0);
    const float4* Wv = (const float4*)W1;
#pragma unroll 4
    for (int k = 0; k < D; k++) {
        float4 wv = Wv[k * 32 + cg];
#pragma unroll
        for (int j = 0; j < 8; j++) {
            float xr = xs[(rg * 8 + j) * D + k];
            acc[j].x = fmaf(xr, wv.x, acc[j].x);
            acc[j].y = fmaf(xr, wv.y, acc[j].y);
            acc[j].z = fmaf(xr, wv.z, acc[j].z);
            acc[j].w = fmaf(xr, wv.w, acc[j].w);
        }
    }
    uint2* S1v = (uint2*)g_S1h;          // 4 halves per uint2
#pragma unroll
    for (int j = 0; j < 8; j++) {
        int r = base + rg * 8 + j;
        if (r < NODES) {
            __half2 h01 = __floats2half2_rn(acc[j].x, acc[j].y);
            __half2 h23 = __floats2half2_rn(acc[j].z, acc[j].w);
            uint2 pk;
            pk.x = *reinterpret_cast<unsigned*>(&h01);
            pk.y = *reinterpret_cast<unsigned*>(&h23);
            S1v[(long long)r * 32 + cg] = pk;
        }
    }
}

// ================= SpMM1 (gather fp16, warp/row) + bias + relu ================
__device__ __forceinline__ void fma4h(float4& acc, float w, uint2 pk) {
    __half2 h01 = *reinterpret_cast<__half2*>(&pk.x);
    __half2 h23 = *reinterpret_cast<__half2*>(&pk.y);
    float2 f01 = __half22float2(h01);
    float2 f23 = __half22float2(h23);
    acc.x = fmaf(w, f01.x, acc.x); acc.y = fmaf(w, f01.y, acc.y);
    acc.z = fmaf(w, f23.x, acc.z); acc.w = fmaf(w, f23.y, acc.w);
}

__global__ void spmm1_kernel(const float* __restrict__ b1) {
    int w = (blockIdx.x * blockDim.x + threadIdx.x) >> 5;
    int lane = threadIdx.x & 31;
    if (w >= NODES) return;
    int i = g_rs[w], end = g_rs[w + 1];
    float4 acc = make_float4(0, 0, 0, 0);
    const uint2* S1v = (const uint2*)g_S1h;
    for (; i + 4 <= end; i += 4) {
        int2 e0 = g_edge[i], e1 = g_edge[i + 1], e2 = g_edge[i + 2], e3 = g_edge[i + 3];
        uint2 v0 = S1v[(long long)e0.x * 32 + lane];
        uint2 v1 = S1v[(long long)e1.x * 32 + lane];
        uint2 v2 = S1v[(long long)e2.x * 32 + lane];
        uint2 v3 = S1v[(long long)e3.x * 32 + lane];
        fma4h(acc, __int_as_float(e0.y), v0);
        fma4h(acc, __int_as_float(e1.y), v1);
        fma4h(acc, __int_as_float(e2.y), v2);
        fma4h(acc, __int_as_float(e3.y), v3);
    }
    for (; i < end; i++) {
        int2 e0 = g_edge[i];
        uint2 v0 = S1v[(long long)e0.x * 32 + lane];
        fma4h(acc, __int_as_float(e0.y), v0);
    }
    float4 bv = ((const float4*)b1)[lane];
    acc.x = fmaxf(acc.x + bv.x, 0.0f);
    acc.y = fmaxf(acc.y + bv.y, 0.0f);
    acc.z = fmaxf(acc.z + bv.z, 0.0f);
    acc.w = fmaxf(acc.w + bv.w, 0.0f);
    ((float4*)g_H)[(long long)w * 32 + lane] = acc;
}

// ================= GEMM2: S2 = H @ W2 (32 rows/block, 160 thr) ================
#define G2_ROWS 32
__global__ void gemm2_kernel(const float* __restrict__ W2) {
    __shared__ float hs[G2_ROWS * D];    // 16 KB
    int base = blockIdx.x * G2_ROWS;
    int tid = threadIdx.x;                // 160
    float4* hsv = (float4*)hs;
    const float4* Hv = (const float4*)g_H;
    for (int i = tid; i < G2_ROWS * 32; i += 160) {
        int rr = i >> 5, cc = i & 31;
        int r = base + rr;
        hsv[i] = (r < NODES) ? Hv[(long long)r * 32 + cc] : make_float4(0, 0, 0, 0);
    }
    __syncthreads();
    int c = tid % C;
    int rg = tid / C;      // 0..3, rows rg*8..+7
    float acc[8];
#pragma unroll
    for (int j = 0; j < 8; j++) acc[j] = 0.0f;
#pragma unroll 4
    for (int k = 0; k < D; k++) {
        float wv = W2[k * C + c];
#pragma unroll
        for (int j = 0; j < 8; j++)
            acc[j] = fmaf(hs[(rg * 8 + j) * D + k], wv, acc[j]);
    }
#pragma unroll
    for (int j = 0; j < 8; j++) {
        int r = base + rg * 8 + j;
        if (r < NODES) g_S2h[(long long)r * C + c] = __float2half_rn(acc[j]);
    }
}

// ============ SpMM2 (gather fp16, 16 lanes/row) + b2 + log_softmax ============
__global__ void spmm2_kernel(const float* __restrict__ b2,
                             float* __restrict__ out) {
    int gt = blockIdx.x * blockDim.x + threadIdx.x;
    int r = gt >> 4;
    int lane16 = gt & 15;
    if (r >= NODES) return;
    bool act = lane16 < 10;              // 10 uint2 chunks (4 halves) cover C=40
    int i = g_rs[r], end = g_rs[r + 1];
    float4 acc = make_float4(0, 0, 0, 0);
    const uint2* S2v = (const uint2*)g_S2h;   // row stride = 10 uint2
    for (; i + 2 <= end; i += 2) {
        int2 e0 = g_edge[i], e1 = g_edge[i + 1];
        if (act) {
            uint2 v0 = S2v[(long long)e0.x * 10 + lane16];
            uint2 v1 = S2v[(long long)e1.x * 10 + lane16];
            fma4h(acc, __int_as_float(e0.y), v0);
            fma4h(acc, __int_as_float(e1.y), v1);
        }
    }
    for (; i < end; i++) {
        int2 e0 = g_edge[i];
        if (act) {
            uint2 v0 = S2v[(long long)e0.x * 10 + lane16];
            fma4h(acc, __int_as_float(e0.y), v0);
        }
    }
    // + bias
    float4 v = make_float4(0, 0, 0, 0);
    if (act) {
        float4 bv = ((const float4*)b2)[lane16];
        v.x = acc.x + bv.x; v.y = acc.y + bv.y;
        v.z = acc.z + bv.z; v.w = acc.w + bv.w;
    }
    // log_softmax over the 40 values held by lanes 0..9 of this 16-lane group
    float m = act ? fmaxf(fmaxf(v.x, v.y), fmaxf(v.z, v.w)) : -CUDART_INF_F;
#pragma unroll
    for (int off = 8; off > 0; off >>= 1)
        m = fmaxf(m, __shfl_xor_sync(0xffffffffu, m, off, 16));
    float s = act ? (__expf(v.x - m) + __expf(v.y - m) +
                     __expf(v.z - m) + __expf(v.w - m)) : 0.0f;
#pragma unroll
    for (int off = 8; off > 0; off >>= 1)
        s += __shfl_xor_sync(0xffffffffu, s, off, 16);
    float lse = m + __logf(s);
    if (act) {
        float4 o;
        o.x = v.x - lse; o.y = v.y - lse; o.z = v.z - lse; o.w = v.w - lse;
        ((float4*)out)[(long long)r * 10 + lane16] = o;
    }
}

// =============================================================================
extern "C" void kernel_launch(void* const* d_in, const int* in_sizes, int n_in,
                              void* d_out, int out_size) {
    const float* x  = (const float*)d_in[0];
    const int*   ei = (const int*)d_in[1];    // delivered as int32
    const float* ew = (const float*)d_in[2];
    const float* W1 = (const float*)d_in[3];
    const float* b1 = (const float*)d_in[4];
    const float* W2 = (const float*)d_in[5];
    const float* b2 = (const float*)d_in[6];
    float* out = (float*)d_out;

    int n = in_sizes[0] / D;      // 50000
    int E = in_sizes[1] / 2;      // 1.6M

    // ---- CSR build ----
    zero_cnt_kernel<<<(SCAN_PAD + 255) / 256, 256>>>();
    hist_kernel<<<(E + 255) / 256, 256>>>(ei, E);
    scanA_kernel<<<SCAN_B, 1024>>>();
    scanC_kernel<<<SCAN_B, 1024>>>();
    scatter_kernel<<<(E + 255) / 256, 256>>>(ei, ew, E);

    // ---- layer 1 ----
    gemm1_kernel<<<(n + G1_ROWS - 1) / G1_ROWS, 256>>>(x, W1);
    {
        long long threads = (long long)n * 32;
        spmm1_kernel<<<(int)((threads + 255) / 256), 256>>>(b1);
    }

    // ---- layer 2 ----
    gemm2_kernel<<<(n + G2_ROWS - 1) / G2_ROWS, 160>>>(W2);
    {
        long long threads = (long long)n * 16;
        spmm2_kernel<<<(int)((threads + 255) / 256), 256>>>(b2, out);
    }
}